// round 12
// baseline (speedup 1.0000x reference)
#include <cuda_runtime.h>
#include <cuda_bf16.h>
#include <cstdint>

#define BB 4
#define NN 8192
#define CIN 64
#define KK 16
#define CO 128
#define NROWS (BB*NN*KK)   /* 524288 */
#define NPTS (BB*NN)       /* 32768  */
#define BN_EPS 1e-5f

typedef unsigned long long ull;

// ---------------- scratch (device globals) ----------------
__device__ float4 g_pts[NPTS];
__device__ int    g_idx[NROWS];
__device__ float  g_fproj[(size_t)NPTS*CO];
__device__ float  g_y2[(size_t)NROWS*CO];
__device__ float  g_part1[2048*256];
__device__ float  g_part2[4096*256];
__device__ float  g_partr[2*64*256];
__device__ float  g_scale1[CO], g_shift1[CO];
__device__ float  g_scale2[CO], g_shift2[CO];

__device__ __forceinline__ uint32_t smem_u32(const void* p) {
    uint32_t a;
    asm("{ .reg .u64 t; cvta.to.shared.u64 t, %1; cvt.u32.u64 %0, t; }"
        : "=r"(a) : "l"(p));
    return a;
}

// ---------------- arch-neutral tensor ops (sm_80+ PTX) ----------------
__device__ __forceinline__ void ldm4(uint32_t* r, uint32_t addr) {
    asm volatile("ldmatrix.sync.aligned.m8n8.x4.shared.b16 {%0,%1,%2,%3}, [%4];"
                 : "=r"(r[0]), "=r"(r[1]), "=r"(r[2]), "=r"(r[3]) : "r"(addr));
}
__device__ __forceinline__ void mma16816(float* c, const uint32_t* a,
                                         const uint32_t* b) {
    asm volatile(
        "mma.sync.aligned.m16n8k16.row.col.f32.bf16.bf16.f32 "
        "{%0,%1,%2,%3}, {%4,%5,%6,%7}, {%8,%9}, {%0,%1,%2,%3};"
        : "+f"(c[0]), "+f"(c[1]), "+f"(c[2]), "+f"(c[3])
        : "r"(a[0]), "r"(a[1]), "r"(a[2]), "r"(a[3]), "r"(b[0]), "r"(b[1]));
}

#define PA 272
#define OFF_AH 0
#define OFF_AL 34816
#define OFF_BH 69632
#define OFF_BL 104448
#define SMEM_T 139264
#define STG_PITCH 132

__device__ __forceinline__ void split_store(char* smem, uint32_t o,
                                            float a, float b) {
    __nv_bfloat16 ah = __float2bfloat16(a), bh = __float2bfloat16(b);
    float al = a - __bfloat162float(ah), bl = b - __bfloat162float(bh);
    *reinterpret_cast<__nv_bfloat162*>(smem + OFF_AH + o) = __halves2bfloat162(ah, bh);
    *reinterpret_cast<__nv_bfloat162*>(smem + OFF_AL + o) =
        __halves2bfloat162(__float2bfloat16(al), __float2bfloat16(bl));
}

__device__ __forceinline__ void w_split(char* smem, const float* __restrict__ W,
                                        int tid) {
    for (int i = tid; i < CO * CO; i += 512) {
        int n = i & 127, k = i >> 7;
        float w = W[k * CO + n];
        __nv_bfloat16 hi = __float2bfloat16(w);
        float lo = w - __bfloat162float(hi);
        uint32_t o = (uint32_t)(n * PA + k * 2);
        *reinterpret_cast<__nv_bfloat16*>(smem + OFF_BH + o) = hi;
        *reinterpret_cast<__nv_bfloat16*>(smem + OFF_BL + o) = __float2bfloat16(lo);
    }
}

// ---------------- K1 ----------------
__global__ void k_prep(const float* __restrict__ pos) {
    int p = blockIdx.x * 128 + threadIdx.x;
    const float* q = pos + (size_t)p * KK * 3;
    float sx = 0.f, sy = 0.f, sz = 0.f;
#pragma unroll
    for (int k = 0; k < KK; k++) { sx += q[k*3]; sy += q[k*3+1]; sz += q[k*3+2]; }
    float x = sx * 0.0625f, y = sy * 0.0625f, z = sz * 0.0625f;
    float sq = fmaf(z, z, fmaf(y, y, x * x));
    g_pts[p] = make_float4(x, y, z, sq);
}

// ---------------- K2: warp-per-query KNN ----------------
// Replicated sorted list per lane. Fast path: warp-uniform binary search for
// the insertion position + unconditional register shift — exactly equal to the
// R2 bubble UNLESS equal real values exist in the list. A real dup is created
// iff inserted vd == dist[p-1] (strict-< insert); sticky flag then routes all
// later inserts of this query through the exact bubble. Sentinel-INF dups are
// harmless (their ids are all 0 on both paths).
template<int S>
__device__ __forceinline__ void bub_from(float (&dist)[KK], int (&id)[KK],
                                         float vd, int vi) {
#pragma unroll
    for (int s = S; s < KK; s++) {
        bool p = vd < dist[s];
        float td = dist[s]; int ti = id[s];
        dist[s] = p ? vd : dist[s];
        id[s]   = p ? vi : id[s];
        vd = p ? td : vd;
        vi = p ? ti : vi;
    }
}

template<int P>
__device__ __forceinline__ bool shift_at(float (&dist)[KK], int (&id)[KK],
                                         float vd, int vi) {
#pragma unroll
    for (int s = KK - 1; s > P; s--) { dist[s] = dist[s-1]; id[s] = id[s-1]; }
    dist[P] = vd; id[P] = vi;
    return (P > 0) ? (vd == dist[P > 0 ? P - 1 : 0]) : false;
}

__device__ __forceinline__ bool fast_insert(float (&dist)[KK], int (&id)[KK],
                                            float vd, int vi) {
    if (vd < dist[7]) {
        if (vd < dist[3]) {
            if (vd < dist[1])
                return (vd < dist[0]) ? shift_at<0>(dist, id, vd, vi)
                                      : shift_at<1>(dist, id, vd, vi);
            else
                return (vd < dist[2]) ? shift_at<2>(dist, id, vd, vi)
                                      : shift_at<3>(dist, id, vd, vi);
        } else {
            if (vd < dist[5])
                return (vd < dist[4]) ? shift_at<4>(dist, id, vd, vi)
                                      : shift_at<5>(dist, id, vd, vi);
            else
                return (vd < dist[6]) ? shift_at<6>(dist, id, vd, vi)
                                      : shift_at<7>(dist, id, vd, vi);
        }
    } else {
        if (vd < dist[11]) {
            if (vd < dist[9])
                return (vd < dist[8]) ? shift_at<8>(dist, id, vd, vi)
                                      : shift_at<9>(dist, id, vd, vi);
            else
                return (vd < dist[10]) ? shift_at<10>(dist, id, vd, vi)
                                       : shift_at<11>(dist, id, vd, vi);
        } else {
            if (vd < dist[13])
                return (vd < dist[12]) ? shift_at<12>(dist, id, vd, vi)
                                       : shift_at<13>(dist, id, vd, vi);
            else
                return (vd < dist[14]) ? shift_at<14>(dist, id, vd, vi)
                                       : shift_at<15>(dist, id, vd, vi);
        }
    }
}

#define QW 8
#define TSZ 1024
__global__ void __launch_bounds__(QW*32) k_knn() {
    __shared__ float4 tile[TSZ];
    const unsigned FULL = 0xffffffffu;
    int lane = threadIdx.x & 31;
    int wid  = threadIdx.x >> 5;
    int b = blockIdx.y;
    int q = blockIdx.x * QW + wid;
    float4 me = g_pts[b * NN + q];

    float dist[KK]; int id[KK];
#pragma unroll
    for (int i = 0; i < KK; i++) { dist[i] = 3.4e38f; id[i] = 0; }
    bool has_dup = false;

    for (int t = 0; t < NN; t += TSZ) {
        __syncthreads();
        for (int i = threadIdx.x; i < TSZ; i += QW*32)
            tile[i] = g_pts[b * NN + t + i];
        __syncthreads();

#pragma unroll 2
        for (int j0 = 0; j0 < TSZ; j0 += 32) {
            float4 c = tile[j0 + lane];
            float dot = fmaf(me.z, c.z, fmaf(me.y, c.y, me.x * c.x));
            float d = fmaf(-2.f, dot, me.w + c.w);
            int cid = t + j0 + lane;

            unsigned mask = __ballot_sync(FULL, d < dist[KK-1]);
            while (mask) {
                int src = __ffs(mask) - 1;
                float vd = __shfl_sync(FULL, d, src);
                int   vi = __shfl_sync(FULL, cid, src);
                if (!has_dup) {
                    has_dup = fast_insert(dist, id, vd, vi);
                } else {
                    bub_from<0>(dist, id, vd, vi);   // exact bubble (tie rotation)
                }
                unsigned above = (src < 31) ? (0xFFFFFFFEu << src) : 0u;
                mask = __ballot_sync(FULL, d < dist[KK-1]) & above;
            }
        }
    }
    if (lane == 0) {
        int4* dst = reinterpret_cast<int4*>(&g_idx[(b * NN + q) * KK]);
        int base = b * NN;
        dst[0] = make_int4(base + id[0],  base + id[1],  base + id[2],  base + id[3]);
        dst[1] = make_int4(base + id[4],  base + id[5],  base + id[6],  base + id[7]);
        dst[2] = make_int4(base + id[8],  base + id[9],  base + id[10], base + id[11]);
        dst[3] = make_int4(base + id[12], base + id[13], base + id[14], base + id[15]);
    }
}

// ---------------- K3: Fproj = b1 + features @ W1[:64,:] ----------------
__global__ void __launch_bounds__(128) k_fproj(const float* __restrict__ feat,
                                               const float* __restrict__ W1,
                                               const float* __restrict__ b1) {
    int c = threadIdx.x;
    int row0 = blockIdx.x * 32;
    __shared__ float fsm[32 * CIN];
    for (int i = c; i < 32 * CIN; i += 128) fsm[i] = feat[(size_t)row0 * CIN + i];
    float wcol[CIN];
#pragma unroll
    for (int f = 0; f < CIN; f++) wcol[f] = W1[f * CO + c];
    float bc = b1[c];
    __syncthreads();
    for (int r = 0; r < 32; r++) {
        float acc = bc;
#pragma unroll
        for (int f = 0; f < CIN; f++) acc = fmaf(fsm[r * CIN + f], wcol[f], acc);
        g_fproj[(size_t)(row0 + r) * CO + c] = acc;
    }
}

__device__ __forceinline__ float y1_val(const float* __restrict__ pos, int row,
                                        int gid, int c, float w0, float w1, float w2) {
    float fp = __ldg(&g_fproj[(size_t)gid * CO + c]);
    const float* pp = pos + (size_t)row * 3;
    return fmaf(__ldg(pp + 2), w2, fmaf(__ldg(pp + 1), w1, fmaf(__ldg(pp), w0, fp)));
}

// ---------------- K4: layer-1 pre-BN stats ----------------
__global__ void __launch_bounds__(256) k_stats1(const float* __restrict__ pos,
                                                const float* __restrict__ W1) {
    __shared__ float red[256];
    int tid = threadIdx.x;
    int c = tid & 127, h = tid >> 7;
    float w0 = W1[64 * CO + c], w1 = W1[65 * CO + c], w2 = W1[66 * CO + c];
    int row0 = blockIdx.x * 256 + h * 128;
    float s = 0.f, ss = 0.f;
#pragma unroll 8
    for (int i = 0; i < 128; i++) {
        int row = row0 + i;
        int gid = __ldg(&g_idx[row]);
        float y = y1_val(pos, row, gid, c, w0, w1, w2);
        s += y; ss = fmaf(y, y, ss);
    }
    __syncthreads();
    if (h == 1) { red[c] = s; red[128 + c] = ss; }
    __syncthreads();
    if (h == 0) {
        g_part1[blockIdx.x * 256 + c]       = s + red[c];
        g_part1[blockIdx.x * 256 + 128 + c] = ss + red[128 + c];
    }
}

// ---------------- stage-1 reduce ----------------
__global__ void __launch_bounds__(256) k_reduce(int which, int per) {
    const float* src = (which == 0) ? g_part1 : g_part2;
    int col = threadIdx.x;
    int b0 = blockIdx.x * per;
    float a = 0.f;
    for (int i = 0; i < per; i++) a += src[(size_t)(b0 + i) * 256 + col];
    g_partr[(size_t)which * 64 * 256 + blockIdx.x * 256 + col] = a;
}

// ---------------- BN finalize ----------------
__global__ void k_bn(int which, const float* __restrict__ gamma,
                     const float* __restrict__ beta) {
    int c = threadIdx.x;
    const float* part = g_partr + (size_t)which * 64 * 256;
    float s = 0.f, ss = 0.f;
#pragma unroll 8
    for (int i = 0; i < 64; i++) {
        s  += part[i * 256 + c];
        ss += part[i * 256 + 128 + c];
    }
    const float inv = 1.f / (float)NROWS;
    float mean = s * inv;
    float var  = fmaf(-mean, mean, ss * inv);
    float sc   = gamma[c] * rsqrtf(var + BN_EPS);
    float sh   = fmaf(-mean, sc, beta[c]);
    if (which == 0) { g_scale1[c] = sc; g_shift1[c] = sh; }
    else            { g_scale2[c] = sc; g_shift2[c] = sh; }
}

// ---------------- shared GEMM core ----------------
__device__ __forceinline__ void gemm_tile(uint32_t sb, int tid, float acc[8][4]) {
    int w = tid >> 5, lane = tid & 31;
    uint32_t a_lane = (uint32_t)((lane & 15) * PA + (lane & 16));
    uint32_t b_lane = (uint32_t)(((lane & 7) + ((lane & 16) >> 1)) * PA
                                 + ((lane & 8) << 1));
    uint32_t m_off = (uint32_t)((w >> 1) * 16 * PA);
    uint32_t n_off = (uint32_t)((w & 1) * 64 * PA);

    const uint32_t abase[3] = {sb + OFF_AH, sb + OFF_AH, sb + OFF_AL};
    const uint32_t bbase[3] = {sb + OFF_BH, sb + OFF_BL, sb + OFF_BH};

#pragma unroll
    for (int t = 0; t < 3; t++) {
        uint32_t ab = abase[t] + m_off + a_lane;
        uint32_t bb = bbase[t] + n_off + b_lane;
#pragma unroll
        for (int ks = 0; ks < 8; ks++) {
            uint32_t a[4];
            ldm4(a, ab + ks * 32);
#pragma unroll
            for (int npl = 0; npl < 4; npl++) {
                uint32_t b[4];
                ldm4(b, bb + npl * 16 * PA + ks * 32);
                mma16816(acc[2 * npl],     a, b);
                mma16816(acc[2 * npl + 1], a, b + 2);
            }
        }
    }
}

// ---------------- K6: layer2 + fused stats2 ----------------
__global__ void __launch_bounds__(512, 1) k_layer2(const float* __restrict__ pos,
                                                   const float* __restrict__ W1,
                                                   const float* __restrict__ W2,
                                                   const float* __restrict__ b2v) {
    extern __shared__ char smem[];
    uint32_t sb = smem_u32(smem);
    int tid = threadIdx.x;
    int rowbase = blockIdx.x * 128;

    w_split(smem, W2, tid);

    int c0 = (tid & 63) * 2;
    int rg6 = tid >> 6;
    float2 w0 = *reinterpret_cast<const float2*>(&W1[64 * CO + c0]);
    float2 w1v = *reinterpret_cast<const float2*>(&W1[65 * CO + c0]);
    float2 w2v = *reinterpret_cast<const float2*>(&W1[66 * CO + c0]);
    float2 sc = make_float2(g_scale1[c0], g_scale1[c0 + 1]);
    float2 sh = make_float2(g_shift1[c0], g_shift1[c0 + 1]);
#pragma unroll 4
    for (int r = 0; r < 16; r++) {
        int m = rg6 * 16 + r;
        int row = rowbase + m;
        int gid = __ldg(&g_idx[row]);
        float2 fp = *reinterpret_cast<const float2*>(&g_fproj[(size_t)gid * CO + c0]);
        const float* pp = pos + (size_t)row * 3;
        float p0 = __ldg(pp), p1 = __ldg(pp + 1), p2 = __ldg(pp + 2);
        float ya = fmaf(p2, w2v.x, fmaf(p1, w1v.x, fmaf(p0, w0.x, fp.x)));
        float yb = fmaf(p2, w2v.y, fmaf(p1, w1v.y, fmaf(p0, w0.y, fp.y)));
        float ha = fmaxf(fmaf(ya, sc.x, sh.x), 0.f);
        float hb = fmaxf(fmaf(yb, sc.y, sh.y), 0.f);
        split_store(smem, (uint32_t)(m * PA + c0 * 2), ha, hb);
    }
    __syncthreads();

    float acc[8][4];
#pragma unroll
    for (int i = 0; i < 8; i++)
#pragma unroll
        for (int j = 0; j < 4; j++) acc[i][j] = 0.f;
    gemm_tile(sb, tid, acc);
    __syncthreads();

    // stage accs -> smem floats
    float* stg = reinterpret_cast<float*>(smem);
    int w = tid >> 5, lane = tid & 31;
    int r = lane >> 2, cq = (lane & 3) * 2;
    int m0 = (w >> 1) * 16;
#pragma unroll
    for (int ntl = 0; ntl < 8; ntl++) {
        int col = ((w & 1) * 8 + ntl) * 8 + cq;
        stg[(m0 + r) * STG_PITCH + col]         = acc[ntl][0];
        stg[(m0 + r) * STG_PITCH + col + 1]     = acc[ntl][1];
        stg[(m0 + r + 8) * STG_PITCH + col]     = acc[ntl][2];
        stg[(m0 + r + 8) * STG_PITCH + col + 1] = acc[ntl][3];
    }
    __syncthreads();

    // coalesced y2 write (+bias) with fused per-channel stats
    int cc = (tid & 31) * 4;
    int rg = tid >> 5;                       // 16 row groups
    float4 bb = *reinterpret_cast<const float4*>(&b2v[cc]);
    float s[4] = {0, 0, 0, 0}, ss[4] = {0, 0, 0, 0};
#pragma unroll
    for (int it = 0; it < 8; it++) {
        int rrow = rg + it * 16;
        float4 v = *reinterpret_cast<float4*>(&stg[rrow * STG_PITCH + cc]);
        v.x += bb.x; v.y += bb.y; v.z += bb.z; v.w += bb.w;
        *reinterpret_cast<float4*>(&g_y2[(size_t)(rowbase + rrow) * CO + cc]) = v;
        s[0] += v.x;  ss[0] = fmaf(v.x, v.x, ss[0]);
        s[1] += v.y;  ss[1] = fmaf(v.y, v.y, ss[1]);
        s[2] += v.z;  ss[2] = fmaf(v.z, v.z, ss[2]);
        s[3] += v.w;  ss[3] = fmaf(v.w, v.w, ss[3]);
    }
    float* red = reinterpret_cast<float*>(smem + OFF_BH);   // B tiles dead now
#pragma unroll
    for (int i = 0; i < 4; i++) {
        red[rg * 128 + cc + i]        = s[i];
        red[2048 + rg * 128 + cc + i] = ss[i];
    }
    __syncthreads();
    if (tid < 128) {
        float a = 0.f;
        for (int g = 0; g < 16; g++) a += red[g * 128 + tid];
        g_part2[(size_t)blockIdx.x * 256 + tid] = a;
    } else if (tid < 256) {
        int ch = tid - 128;
        float a = 0.f;
        for (int g = 0; g < 16; g++) a += red[2048 + g * 128 + ch];
        g_part2[(size_t)blockIdx.x * 256 + 128 + ch] = a;
    }
}

// ---------------- K8: layer3 -> max over K (+b3) ----------------
__global__ void __launch_bounds__(512, 1) k_layer3(const float* __restrict__ W3,
                                                   const float* __restrict__ b3v,
                                                   float* __restrict__ out) {
    extern __shared__ char smem[];
    uint32_t sb = smem_u32(smem);
    int tid = threadIdx.x;
    int rowbase = blockIdx.x * 128;

    w_split(smem, W3, tid);

    int c0 = (tid & 63) * 2;
    int rg6 = tid >> 6;
    float2 sc = make_float2(g_scale2[c0], g_scale2[c0 + 1]);
    float2 sh = make_float2(g_shift2[c0], g_shift2[c0 + 1]);
#pragma unroll 4
    for (int r = 0; r < 16; r++) {
        int m = rg6 * 16 + r;
        float2 y = *reinterpret_cast<const float2*>(
            &g_y2[(size_t)(rowbase + m) * CO + c0]);
        float ha = fmaxf(fmaf(y.x, sc.x, sh.x), 0.f);
        float hb = fmaxf(fmaf(y.y, sc.y, sh.y), 0.f);
        split_store(smem, (uint32_t)(m * PA + c0 * 2), ha, hb);
    }
    __syncthreads();

    float acc[8][4];
#pragma unroll
    for (int i = 0; i < 8; i++)
#pragma unroll
        for (int j = 0; j < 4; j++) acc[i][j] = 0.f;
    gemm_tile(sb, tid, acc);

    int w = tid >> 5, lane = tid & 31;
    float cm0[8], cm1[8];
#pragma unroll
    for (int ntl = 0; ntl < 8; ntl++) {
        cm0[ntl] = fmaxf(acc[ntl][0], acc[ntl][2]);
        cm1[ntl] = fmaxf(acc[ntl][1], acc[ntl][3]);
    }
#pragma unroll
    for (int off = 4; off < 32; off <<= 1) {
#pragma unroll
        for (int ntl = 0; ntl < 8; ntl++) {
            cm0[ntl] = fmaxf(cm0[ntl], __shfl_xor_sync(0xffffffffu, cm0[ntl], off));
            cm1[ntl] = fmaxf(cm1[ntl], __shfl_xor_sync(0xffffffffu, cm1[ntl], off));
        }
    }
    if (lane < 4) {
        int p = (rowbase >> 4) + (w >> 1);
#pragma unroll
        for (int ntl = 0; ntl < 8; ntl++) {
            int col = ((w & 1) * 8 + ntl) * 8 + lane * 2;
            out[(size_t)p * CO + col]     = cm0[ntl] + __ldg(&b3v[col]);
            out[(size_t)p * CO + col + 1] = cm1[ntl] + __ldg(&b3v[col + 1]);
        }
    }
}

// ---------------- launch ----------------
extern "C" void kernel_launch(void* const* d_in, const int* in_sizes, int n_in,
                              void* d_out, int out_size) {
    const float* features = (const float*)d_in[0];
    const float* pos      = (const float*)d_in[1];
    const float* W1  = (const float*)d_in[2];
    const float* b1  = (const float*)d_in[3];
    const float* g1  = (const float*)d_in[4];
    const float* bt1 = (const float*)d_in[5];
    const float* W2  = (const float*)d_in[6];
    const float* b2  = (const float*)d_in[7];
    const float* g2  = (const float*)d_in[8];
    const float* bt2 = (const float*)d_in[9];
    const float* W3  = (const float*)d_in[10];
    const float* b3  = (const float*)d_in[11];
    float* out = (float*)d_out;

    cudaFuncSetAttribute(k_layer2, cudaFuncAttributeMaxDynamicSharedMemorySize, SMEM_T);
    cudaFuncSetAttribute(k_layer3, cudaFuncAttributeMaxDynamicSharedMemorySize, SMEM_T);

    // order keeps k_knn as the 4th (profiled) launch
    k_prep<<<NPTS / 128, 128>>>(pos);
    k_fproj<<<NPTS / 32, 128>>>(features, W1, b1);
    k_prep<<<NPTS / 128, 128>>>(pos);         // idempotent filler
    k_knn<<<dim3(NN / QW, BB), QW * 32>>>();
    k_stats1<<<2048, 256>>>(pos, W1);
    k_reduce<<<64, 256>>>(0, 32);
    k_bn<<<1, 128>>>(0, g1, bt1);
    k_layer2<<<NROWS / 128, 512, SMEM_T>>>(pos, W1, W2, b2);
    k_reduce<<<64, 256>>>(1, 64);
    k_bn<<<1, 128>>>(1, g2, bt2);
    k_layer3<<<NROWS / 128, 512, SMEM_T>>>(W3, b3, out);
}

// round 13
// speedup vs baseline: 1.1087x; 1.1087x over previous
#include <cuda_runtime.h>
#include <cuda_bf16.h>
#include <cstdint>

#define BB 4
#define NN 8192
#define CIN 64
#define KK 16
#define CO 128
#define NROWS (BB*NN*KK)   /* 524288 */
#define NPTS (BB*NN)       /* 32768  */
#define BN_EPS 1e-5f

typedef unsigned long long ull;

// ---------------- scratch (device globals) ----------------
__device__ float4 g_pts[NPTS];
__device__ int    g_idx[NROWS];
__device__ float  g_fproj[(size_t)NPTS*CO];
__device__ float  g_y2[(size_t)NROWS*CO];
__device__ float  g_part1[2048*256];
__device__ float  g_part2[4096*256];
__device__ float  g_partr[2*64*256];
__device__ float  g_scale1[CO], g_shift1[CO];
__device__ float  g_scale2[CO], g_shift2[CO];

__device__ __forceinline__ uint32_t smem_u32(const void* p) {
    uint32_t a;
    asm("{ .reg .u64 t; cvta.to.shared.u64 t, %1; cvt.u32.u64 %0, t; }"
        : "=r"(a) : "l"(p));
    return a;
}

// ---------------- arch-neutral tensor ops (sm_80+ PTX) ----------------
__device__ __forceinline__ void ldm4(uint32_t* r, uint32_t addr) {
    asm volatile("ldmatrix.sync.aligned.m8n8.x4.shared.b16 {%0,%1,%2,%3}, [%4];"
                 : "=r"(r[0]), "=r"(r[1]), "=r"(r[2]), "=r"(r[3]) : "r"(addr));
}
__device__ __forceinline__ void mma16816(float* c, const uint32_t* a,
                                         const uint32_t* b) {
    asm volatile(
        "mma.sync.aligned.m16n8k16.row.col.f32.bf16.bf16.f32 "
        "{%0,%1,%2,%3}, {%4,%5,%6,%7}, {%8,%9}, {%0,%1,%2,%3};"
        : "+f"(c[0]), "+f"(c[1]), "+f"(c[2]), "+f"(c[3])
        : "r"(a[0]), "r"(a[1]), "r"(a[2]), "r"(a[3]), "r"(b[0]), "r"(b[1]));
}

#define PA 272
#define OFF_AH 0
#define OFF_AL 34816
#define OFF_BH 69632
#define OFF_BL 104448
#define SMEM_T 139264
#define STG_PITCH 132

__device__ __forceinline__ void split_store(char* smem, uint32_t o,
                                            float a, float b) {
    __nv_bfloat16 ah = __float2bfloat16(a), bh = __float2bfloat16(b);
    float al = a - __bfloat162float(ah), bl = b - __bfloat162float(bh);
    *reinterpret_cast<__nv_bfloat162*>(smem + OFF_AH + o) = __halves2bfloat162(ah, bh);
    *reinterpret_cast<__nv_bfloat162*>(smem + OFF_AL + o) =
        __halves2bfloat162(__float2bfloat16(al), __float2bfloat16(bl));
}

__device__ __forceinline__ void w_split(char* smem, const float* __restrict__ W,
                                        int tid) {
    for (int i = tid; i < CO * CO; i += 512) {
        int n = i & 127, k = i >> 7;
        float w = W[k * CO + n];
        __nv_bfloat16 hi = __float2bfloat16(w);
        float lo = w - __bfloat162float(hi);
        uint32_t o = (uint32_t)(n * PA + k * 2);
        *reinterpret_cast<__nv_bfloat16*>(smem + OFF_BH + o) = hi;
        *reinterpret_cast<__nv_bfloat16*>(smem + OFF_BL + o) = __float2bfloat16(lo);
    }
}

// ---------------- K1 ----------------
__global__ void k_prep(const float* __restrict__ pos) {
    int p = blockIdx.x * 128 + threadIdx.x;
    const float* q = pos + (size_t)p * KK * 3;
    float sx = 0.f, sy = 0.f, sz = 0.f;
#pragma unroll
    for (int k = 0; k < KK; k++) { sx += q[k*3]; sy += q[k*3+1]; sz += q[k*3+2]; }
    float x = sx * 0.0625f, y = sy * 0.0625f, z = sz * 0.0625f;
    float sq = fmaf(z, z, fmaf(y, y, x * x));
    g_pts[p] = make_float4(x, y, z, sq);
}

// ---------------- K2: warp-per-query KNN, replicated-list bubble (R11, proven) --
template<int S>
__device__ __forceinline__ void bub_from(float (&dist)[KK], int (&id)[KK],
                                         float vd, int vi) {
#pragma unroll
    for (int s = S; s < KK; s++) {
        bool p = vd < dist[s];
        float td = dist[s]; int ti = id[s];
        dist[s] = p ? vd : dist[s];
        id[s]   = p ? vi : id[s];
        vd = p ? td : vd;
        vi = p ? ti : vi;
    }
}

#define QW 8
#define TSZ 1024
__global__ void __launch_bounds__(QW*32) k_knn() {
    __shared__ float4 tile[TSZ];
    const unsigned FULL = 0xffffffffu;
    int lane = threadIdx.x & 31;
    int wid  = threadIdx.x >> 5;
    int b = blockIdx.y;
    int q = blockIdx.x * QW + wid;
    float4 me = g_pts[b * NN + q];

    float dist[KK]; int id[KK];
#pragma unroll
    for (int i = 0; i < KK; i++) { dist[i] = 3.4e38f; id[i] = 0; }

    for (int t = 0; t < NN; t += TSZ) {
        __syncthreads();
        for (int i = threadIdx.x; i < TSZ; i += QW*32)
            tile[i] = g_pts[b * NN + t + i];
        __syncthreads();

        for (int j0 = 0; j0 < TSZ; j0 += 32) {
            float4 c = tile[j0 + lane];
            float dot = fmaf(me.z, c.z, fmaf(me.y, c.y, me.x * c.x));
            float d = fmaf(-2.f, dot, me.w + c.w);
            int cid = t + j0 + lane;

            unsigned mask = __ballot_sync(FULL, d < dist[KK-1]);
            while (mask) {
                int src = __ffs(mask) - 1;
                float vd = __shfl_sync(FULL, d, src);
                int   vi = __shfl_sync(FULL, cid, src);
                if (vd < dist[7]) {
                    if (vd < dist[3]) bub_from<0>(dist, id, vd, vi);
                    else              bub_from<4>(dist, id, vd, vi);
                } else {
                    if (vd < dist[11]) bub_from<8>(dist, id, vd, vi);
                    else               bub_from<12>(dist, id, vd, vi);
                }
                unsigned above = (src < 31) ? (0xFFFFFFFEu << src) : 0u;
                mask = __ballot_sync(FULL, d < dist[KK-1]) & above;
            }
        }
    }
    if (lane == 0) {
        int4* dst = reinterpret_cast<int4*>(&g_idx[(b * NN + q) * KK]);
        int base = b * NN;
        dst[0] = make_int4(base + id[0],  base + id[1],  base + id[2],  base + id[3]);
        dst[1] = make_int4(base + id[4],  base + id[5],  base + id[6],  base + id[7]);
        dst[2] = make_int4(base + id[8],  base + id[9],  base + id[10], base + id[11]);
        dst[3] = make_int4(base + id[12], base + id[13], base + id[14], base + id[15]);
    }
}

// ---------------- K3: Fproj = b1 + features @ W1[:64,:] ----------------
__global__ void __launch_bounds__(128) k_fproj(const float* __restrict__ feat,
                                               const float* __restrict__ W1,
                                               const float* __restrict__ b1) {
    int c = threadIdx.x;
    int row0 = blockIdx.x * 32;
    __shared__ float fsm[32 * CIN];
    for (int i = c; i < 32 * CIN; i += 128) fsm[i] = feat[(size_t)row0 * CIN + i];
    float wcol[CIN];
#pragma unroll
    for (int f = 0; f < CIN; f++) wcol[f] = W1[f * CO + c];
    float bc = b1[c];
    __syncthreads();
    for (int r = 0; r < 32; r++) {
        float acc = bc;
#pragma unroll
        for (int f = 0; f < CIN; f++) acc = fmaf(fsm[r * CIN + f], wcol[f], acc);
        g_fproj[(size_t)(row0 + r) * CO + c] = acc;
    }
}

__device__ __forceinline__ float y1_val(const float* __restrict__ pos, int row,
                                        int gid, int c, float w0, float w1, float w2) {
    float fp = __ldg(&g_fproj[(size_t)gid * CO + c]);
    const float* pp = pos + (size_t)row * 3;
    return fmaf(__ldg(pp + 2), w2, fmaf(__ldg(pp + 1), w1, fmaf(__ldg(pp), w0, fp)));
}

// ---------------- K4: layer-1 pre-BN stats ----------------
__global__ void __launch_bounds__(256) k_stats1(const float* __restrict__ pos,
                                                const float* __restrict__ W1) {
    __shared__ float red[256];
    int tid = threadIdx.x;
    int c = tid & 127, h = tid >> 7;
    float w0 = W1[64 * CO + c], w1 = W1[65 * CO + c], w2 = W1[66 * CO + c];
    int row0 = blockIdx.x * 256 + h * 128;
    float s = 0.f, ss = 0.f;
#pragma unroll 8
    for (int i = 0; i < 128; i++) {
        int row = row0 + i;
        int gid = __ldg(&g_idx[row]);
        float y = y1_val(pos, row, gid, c, w0, w1, w2);
        s += y; ss = fmaf(y, y, ss);
    }
    __syncthreads();
    if (h == 1) { red[c] = s; red[128 + c] = ss; }
    __syncthreads();
    if (h == 0) {
        g_part1[blockIdx.x * 256 + c]       = s + red[c];
        g_part1[blockIdx.x * 256 + 128 + c] = ss + red[128 + c];
    }
}

// ---------------- stage-1 reduce ----------------
__global__ void __launch_bounds__(256) k_reduce(int which, int per) {
    const float* src = (which == 0) ? g_part1 : g_part2;
    int col = threadIdx.x;
    int b0 = blockIdx.x * per;
    float a = 0.f;
    for (int i = 0; i < per; i++) a += src[(size_t)(b0 + i) * 256 + col];
    g_partr[(size_t)which * 64 * 256 + blockIdx.x * 256 + col] = a;
}

// ---------------- BN finalize ----------------
__global__ void k_bn(int which, const float* __restrict__ gamma,
                     const float* __restrict__ beta) {
    int c = threadIdx.x;
    const float* part = g_partr + (size_t)which * 64 * 256;
    float s = 0.f, ss = 0.f;
#pragma unroll 8
    for (int i = 0; i < 64; i++) {
        s  += part[i * 256 + c];
        ss += part[i * 256 + 128 + c];
    }
    const float inv = 1.f / (float)NROWS;
    float mean = s * inv;
    float var  = fmaf(-mean, mean, ss * inv);
    float sc   = gamma[c] * rsqrtf(var + BN_EPS);
    float sh   = fmaf(-mean, sc, beta[c]);
    if (which == 0) { g_scale1[c] = sc; g_shift1[c] = sh; }
    else            { g_scale2[c] = sc; g_shift2[c] = sh; }
}

// ---------------- shared GEMM core ----------------
__device__ __forceinline__ void gemm_tile(uint32_t sb, int tid, float acc[8][4]) {
    int w = tid >> 5, lane = tid & 31;
    uint32_t a_lane = (uint32_t)((lane & 15) * PA + (lane & 16));
    uint32_t b_lane = (uint32_t)(((lane & 7) + ((lane & 16) >> 1)) * PA
                                 + ((lane & 8) << 1));
    uint32_t m_off = (uint32_t)((w >> 1) * 16 * PA);
    uint32_t n_off = (uint32_t)((w & 1) * 64 * PA);

    const uint32_t abase[3] = {sb + OFF_AH, sb + OFF_AH, sb + OFF_AL};
    const uint32_t bbase[3] = {sb + OFF_BH, sb + OFF_BL, sb + OFF_BH};

#pragma unroll
    for (int t = 0; t < 3; t++) {
        uint32_t ab = abase[t] + m_off + a_lane;
        uint32_t bb = bbase[t] + n_off + b_lane;
#pragma unroll
        for (int ks = 0; ks < 8; ks++) {
            uint32_t a[4];
            ldm4(a, ab + ks * 32);
#pragma unroll
            for (int npl = 0; npl < 4; npl++) {
                uint32_t b[4];
                ldm4(b, bb + npl * 16 * PA + ks * 32);
                mma16816(acc[2 * npl],     a, b);
                mma16816(acc[2 * npl + 1], a, b + 2);
            }
        }
    }
}

// ---------------- K6: layer2 + fused stats2 ----------------
__global__ void __launch_bounds__(512, 1) k_layer2(const float* __restrict__ pos,
                                                   const float* __restrict__ W1,
                                                   const float* __restrict__ W2,
                                                   const float* __restrict__ b2v) {
    extern __shared__ char smem[];
    uint32_t sb = smem_u32(smem);
    int tid = threadIdx.x;
    int rowbase = blockIdx.x * 128;

    w_split(smem, W2, tid);

    int c0 = (tid & 63) * 2;
    int rg6 = tid >> 6;
    float2 w0 = *reinterpret_cast<const float2*>(&W1[64 * CO + c0]);
    float2 w1v = *reinterpret_cast<const float2*>(&W1[65 * CO + c0]);
    float2 w2v = *reinterpret_cast<const float2*>(&W1[66 * CO + c0]);
    float2 sc = make_float2(g_scale1[c0], g_scale1[c0 + 1]);
    float2 sh = make_float2(g_shift1[c0], g_shift1[c0 + 1]);
#pragma unroll 4
    for (int r = 0; r < 16; r++) {
        int m = rg6 * 16 + r;
        int row = rowbase + m;
        int gid = __ldg(&g_idx[row]);
        float2 fp = *reinterpret_cast<const float2*>(&g_fproj[(size_t)gid * CO + c0]);
        const float* pp = pos + (size_t)row * 3;
        float p0 = __ldg(pp), p1 = __ldg(pp + 1), p2 = __ldg(pp + 2);
        float ya = fmaf(p2, w2v.x, fmaf(p1, w1v.x, fmaf(p0, w0.x, fp.x)));
        float yb = fmaf(p2, w2v.y, fmaf(p1, w1v.y, fmaf(p0, w0.y, fp.y)));
        float ha = fmaxf(fmaf(ya, sc.x, sh.x), 0.f);
        float hb = fmaxf(fmaf(yb, sc.y, sh.y), 0.f);
        split_store(smem, (uint32_t)(m * PA + c0 * 2), ha, hb);
    }
    __syncthreads();

    float acc[8][4];
#pragma unroll
    for (int i = 0; i < 8; i++)
#pragma unroll
        for (int j = 0; j < 4; j++) acc[i][j] = 0.f;
    gemm_tile(sb, tid, acc);
    __syncthreads();

    // stage accs -> smem floats
    float* stg = reinterpret_cast<float*>(smem);
    int w = tid >> 5, lane = tid & 31;
    int r = lane >> 2, cq = (lane & 3) * 2;
    int m0 = (w >> 1) * 16;
#pragma unroll
    for (int ntl = 0; ntl < 8; ntl++) {
        int col = ((w & 1) * 8 + ntl) * 8 + cq;
        stg[(m0 + r) * STG_PITCH + col]         = acc[ntl][0];
        stg[(m0 + r) * STG_PITCH + col + 1]     = acc[ntl][1];
        stg[(m0 + r + 8) * STG_PITCH + col]     = acc[ntl][2];
        stg[(m0 + r + 8) * STG_PITCH + col + 1] = acc[ntl][3];
    }
    __syncthreads();

    // coalesced y2 write (+bias) with fused per-channel stats
    int cc = (tid & 31) * 4;
    int rg = tid >> 5;                       // 16 row groups
    float4 bb = *reinterpret_cast<const float4*>(&b2v[cc]);
    float s[4] = {0, 0, 0, 0}, ss[4] = {0, 0, 0, 0};
#pragma unroll
    for (int it = 0; it < 8; it++) {
        int rrow = rg + it * 16;
        float4 v = *reinterpret_cast<float4*>(&stg[rrow * STG_PITCH + cc]);
        v.x += bb.x; v.y += bb.y; v.z += bb.z; v.w += bb.w;
        *reinterpret_cast<float4*>(&g_y2[(size_t)(rowbase + rrow) * CO + cc]) = v;
        s[0] += v.x;  ss[0] = fmaf(v.x, v.x, ss[0]);
        s[1] += v.y;  ss[1] = fmaf(v.y, v.y, ss[1]);
        s[2] += v.z;  ss[2] = fmaf(v.z, v.z, ss[2]);
        s[3] += v.w;  ss[3] = fmaf(v.w, v.w, ss[3]);
    }
    float* red = reinterpret_cast<float*>(smem + OFF_BH);   // B tiles dead now
#pragma unroll
    for (int i = 0; i < 4; i++) {
        red[rg * 128 + cc + i]        = s[i];
        red[2048 + rg * 128 + cc + i] = ss[i];
    }
    __syncthreads();
    if (tid < 128) {
        float a = 0.f;
        for (int g = 0; g < 16; g++) a += red[g * 128 + tid];
        g_part2[(size_t)blockIdx.x * 256 + tid] = a;
    } else if (tid < 256) {
        int ch = tid - 128;
        float a = 0.f;
        for (int g = 0; g < 16; g++) a += red[2048 + g * 128 + ch];
        g_part2[(size_t)blockIdx.x * 256 + 128 + ch] = a;
    }
}

// ---------------- K8: layer3 -> max over K (+b3) ----------------
__global__ void __launch_bounds__(512, 1) k_layer3(const float* __restrict__ W3,
                                                   const float* __restrict__ b3v,
                                                   float* __restrict__ out) {
    extern __shared__ char smem[];
    uint32_t sb = smem_u32(smem);
    int tid = threadIdx.x;
    int rowbase = blockIdx.x * 128;

    w_split(smem, W3, tid);

    int c0 = (tid & 63) * 2;
    int rg6 = tid >> 6;
    float2 sc = make_float2(g_scale2[c0], g_scale2[c0 + 1]);
    float2 sh = make_float2(g_shift2[c0], g_shift2[c0 + 1]);
#pragma unroll 4
    for (int r = 0; r < 16; r++) {
        int m = rg6 * 16 + r;
        float2 y = *reinterpret_cast<const float2*>(
            &g_y2[(size_t)(rowbase + m) * CO + c0]);
        float ha = fmaxf(fmaf(y.x, sc.x, sh.x), 0.f);
        float hb = fmaxf(fmaf(y.y, sc.y, sh.y), 0.f);
        split_store(smem, (uint32_t)(m * PA + c0 * 2), ha, hb);
    }
    __syncthreads();

    float acc[8][4];
#pragma unroll
    for (int i = 0; i < 8; i++)
#pragma unroll
        for (int j = 0; j < 4; j++) acc[i][j] = 0.f;
    gemm_tile(sb, tid, acc);

    int w = tid >> 5, lane = tid & 31;
    float cm0[8], cm1[8];
#pragma unroll
    for (int ntl = 0; ntl < 8; ntl++) {
        cm0[ntl] = fmaxf(acc[ntl][0], acc[ntl][2]);
        cm1[ntl] = fmaxf(acc[ntl][1], acc[ntl][3]);
    }
#pragma unroll
    for (int off = 4; off < 32; off <<= 1) {
#pragma unroll
        for (int ntl = 0; ntl < 8; ntl++) {
            cm0[ntl] = fmaxf(cm0[ntl], __shfl_xor_sync(0xffffffffu, cm0[ntl], off));
            cm1[ntl] = fmaxf(cm1[ntl], __shfl_xor_sync(0xffffffffu, cm1[ntl], off));
        }
    }
    if (lane < 4) {
        int p = (rowbase >> 4) + (w >> 1);
#pragma unroll
        for (int ntl = 0; ntl < 8; ntl++) {
            int col = ((w & 1) * 8 + ntl) * 8 + lane * 2;
            out[(size_t)p * CO + col]     = cm0[ntl] + __ldg(&b3v[col]);
            out[(size_t)p * CO + col + 1] = cm1[ntl] + __ldg(&b3v[col + 1]);
        }
    }
}

// ---------------- launch ----------------
extern "C" void kernel_launch(void* const* d_in, const int* in_sizes, int n_in,
                              void* d_out, int out_size) {
    const float* features = (const float*)d_in[0];
    const float* pos      = (const float*)d_in[1];
    const float* W1  = (const float*)d_in[2];
    const float* b1  = (const float*)d_in[3];
    const float* g1  = (const float*)d_in[4];
    const float* bt1 = (const float*)d_in[5];
    const float* W2  = (const float*)d_in[6];
    const float* b2  = (const float*)d_in[7];
    const float* g2  = (const float*)d_in[8];
    const float* bt2 = (const float*)d_in[9];
    const float* W3  = (const float*)d_in[10];
    const float* b3  = (const float*)d_in[11];
    float* out = (float*)d_out;

    cudaFuncSetAttribute(k_layer2, cudaFuncAttributeMaxDynamicSharedMemorySize, SMEM_T);
    cudaFuncSetAttribute(k_layer3, cudaFuncAttributeMaxDynamicSharedMemorySize, SMEM_T);

    // order keeps k_knn as the 4th (profiled) launch
    k_prep<<<NPTS / 128, 128>>>(pos);
    k_fproj<<<NPTS / 32, 128>>>(features, W1, b1);
    k_prep<<<NPTS / 128, 128>>>(pos);         // idempotent filler
    k_knn<<<dim3(NN / QW, BB), QW * 32>>>();
    k_stats1<<<2048, 256>>>(pos, W1);
    k_reduce<<<64, 256>>>(0, 32);
    k_bn<<<1, 128>>>(0, g1, bt1);
    k_layer2<<<NROWS / 128, 512, SMEM_T>>>(pos, W1, W2, b2);
    k_reduce<<<64, 256>>>(1, 64);
    k_bn<<<1, 128>>>(1, g2, bt2);
    k_layer3<<<NROWS / 128, 512, SMEM_T>>>(W3, b3, out);
}

// round 14
// speedup vs baseline: 1.1634x; 1.0494x over previous
#include <cuda_runtime.h>
#include <cuda_bf16.h>
#include <cstdint>

#define BB 4
#define NN 8192
#define CIN 64
#define KK 16
#define CO 128
#define NROWS (BB*NN*KK)   /* 524288 */
#define NPTS (BB*NN)       /* 32768  */
#define BN_EPS 1e-5f

typedef unsigned long long ull;

// ---------------- scratch (device globals) ----------------
__device__ float4 g_pts[NPTS];
__device__ int    g_idx[NROWS];
__device__ float  g_fproj[(size_t)NPTS*CO];
__device__ float  g_y2[(size_t)NROWS*CO];
__device__ float  g_part1[2048*256];
__device__ float  g_part2[4096*256];
__device__ float  g_partr[2*64*256];
__device__ float  g_scale1[CO], g_shift1[CO];
__device__ float  g_scale2[CO], g_shift2[CO];

__device__ __forceinline__ uint32_t smem_u32(const void* p) {
    uint32_t a;
    asm("{ .reg .u64 t; cvta.to.shared.u64 t, %1; cvt.u32.u64 %0, t; }"
        : "=r"(a) : "l"(p));
    return a;
}

// ---------------- arch-neutral tensor ops (sm_80+ PTX) ----------------
__device__ __forceinline__ void ldm4(uint32_t* r, uint32_t addr) {
    asm volatile("ldmatrix.sync.aligned.m8n8.x4.shared.b16 {%0,%1,%2,%3}, [%4];"
                 : "=r"(r[0]), "=r"(r[1]), "=r"(r[2]), "=r"(r[3]) : "r"(addr));
}
__device__ __forceinline__ void mma16816(float* c, const uint32_t* a,
                                         const uint32_t* b) {
    asm volatile(
        "mma.sync.aligned.m16n8k16.row.col.f32.bf16.bf16.f32 "
        "{%0,%1,%2,%3}, {%4,%5,%6,%7}, {%8,%9}, {%0,%1,%2,%3};"
        : "+f"(c[0]), "+f"(c[1]), "+f"(c[2]), "+f"(c[3])
        : "r"(a[0]), "r"(a[1]), "r"(a[2]), "r"(a[3]), "r"(b[0]), "r"(b[1]));
}

#define PA 272
#define OFF_AH 0
#define OFF_AL 34816
#define OFF_BH 69632
#define OFF_BL 104448
#define SMEM_T 139264
#define STG_PITCH 132
#define CHUNKS 4
#define ROWS_PB (128 * CHUNKS)    /* 512 rows per block */

__device__ __forceinline__ void split_store(char* smem, uint32_t o,
                                            float a, float b) {
    __nv_bfloat16 ah = __float2bfloat16(a), bh = __float2bfloat16(b);
    float al = a - __bfloat162float(ah), bl = b - __bfloat162float(bh);
    *reinterpret_cast<__nv_bfloat162*>(smem + OFF_AH + o) = __halves2bfloat162(ah, bh);
    *reinterpret_cast<__nv_bfloat162*>(smem + OFF_AL + o) =
        __halves2bfloat162(__float2bfloat16(al), __float2bfloat16(bl));
}

__device__ __forceinline__ void w_split(char* smem, const float* __restrict__ W,
                                        int tid) {
    for (int i = tid; i < CO * CO; i += 512) {
        int n = i & 127, k = i >> 7;
        float w = W[k * CO + n];
        __nv_bfloat16 hi = __float2bfloat16(w);
        float lo = w - __bfloat162float(hi);
        uint32_t o = (uint32_t)(n * PA + k * 2);
        *reinterpret_cast<__nv_bfloat16*>(smem + OFF_BH + o) = hi;
        *reinterpret_cast<__nv_bfloat16*>(smem + OFF_BL + o) = __float2bfloat16(lo);
    }
}

// ---------------- K1 ----------------
__global__ void k_prep(const float* __restrict__ pos) {
    int p = blockIdx.x * 128 + threadIdx.x;
    const float* q = pos + (size_t)p * KK * 3;
    float sx = 0.f, sy = 0.f, sz = 0.f;
#pragma unroll
    for (int k = 0; k < KK; k++) { sx += q[k*3]; sy += q[k*3+1]; sz += q[k*3+2]; }
    float x = sx * 0.0625f, y = sy * 0.0625f, z = sz * 0.0625f;
    float sq = fmaf(z, z, fmaf(y, y, x * x));
    g_pts[p] = make_float4(x, y, z, sq);
}

// ---------------- K2: warp-per-query KNN, replicated-list bubble (proven) -------
template<int S>
__device__ __forceinline__ void bub_from(float (&dist)[KK], int (&id)[KK],
                                         float vd, int vi) {
#pragma unroll
    for (int s = S; s < KK; s++) {
        bool p = vd < dist[s];
        float td = dist[s]; int ti = id[s];
        dist[s] = p ? vd : dist[s];
        id[s]   = p ? vi : id[s];
        vd = p ? td : vd;
        vi = p ? ti : vi;
    }
}

#define QW 8
#define TSZ 1024
__global__ void __launch_bounds__(QW*32) k_knn() {
    __shared__ float4 tile[TSZ];
    const unsigned FULL = 0xffffffffu;
    int lane = threadIdx.x & 31;
    int wid  = threadIdx.x >> 5;
    int b = blockIdx.y;
    int q = blockIdx.x * QW + wid;
    float4 me = g_pts[b * NN + q];

    float dist[KK]; int id[KK];
#pragma unroll
    for (int i = 0; i < KK; i++) { dist[i] = 3.4e38f; id[i] = 0; }

    for (int t = 0; t < NN; t += TSZ) {
        __syncthreads();
        for (int i = threadIdx.x; i < TSZ; i += QW*32)
            tile[i] = g_pts[b * NN + t + i];
        __syncthreads();

        for (int j0 = 0; j0 < TSZ; j0 += 32) {
            float4 c = tile[j0 + lane];
            float dot = fmaf(me.z, c.z, fmaf(me.y, c.y, me.x * c.x));
            float d = fmaf(-2.f, dot, me.w + c.w);
            int cid = t + j0 + lane;

            unsigned mask = __ballot_sync(FULL, d < dist[KK-1]);
            while (mask) {
                int src = __ffs(mask) - 1;
                float vd = __shfl_sync(FULL, d, src);
                int   vi = __shfl_sync(FULL, cid, src);
                if (vd < dist[7]) {
                    if (vd < dist[3]) bub_from<0>(dist, id, vd, vi);
                    else              bub_from<4>(dist, id, vd, vi);
                } else {
                    if (vd < dist[11]) bub_from<8>(dist, id, vd, vi);
                    else               bub_from<12>(dist, id, vd, vi);
                }
                unsigned above = (src < 31) ? (0xFFFFFFFEu << src) : 0u;
                mask = __ballot_sync(FULL, d < dist[KK-1]) & above;
            }
        }
    }
    if (lane == 0) {
        int4* dst = reinterpret_cast<int4*>(&g_idx[(b * NN + q) * KK]);
        int base = b * NN;
        dst[0] = make_int4(base + id[0],  base + id[1],  base + id[2],  base + id[3]);
        dst[1] = make_int4(base + id[4],  base + id[5],  base + id[6],  base + id[7]);
        dst[2] = make_int4(base + id[8],  base + id[9],  base + id[10], base + id[11]);
        dst[3] = make_int4(base + id[12], base + id[13], base + id[14], base + id[15]);
    }
}

// ---------------- K3: Fproj = b1 + features @ W1[:64,:] ----------------
__global__ void __launch_bounds__(128) k_fproj(const float* __restrict__ feat,
                                               const float* __restrict__ W1,
                                               const float* __restrict__ b1) {
    int c = threadIdx.x;
    int row0 = blockIdx.x * 32;
    __shared__ float fsm[32 * CIN];
    for (int i = c; i < 32 * CIN; i += 128) fsm[i] = feat[(size_t)row0 * CIN + i];
    float wcol[CIN];
#pragma unroll
    for (int f = 0; f < CIN; f++) wcol[f] = W1[f * CO + c];
    float bc = b1[c];
    __syncthreads();
    for (int r = 0; r < 32; r++) {
        float acc = bc;
#pragma unroll
        for (int f = 0; f < CIN; f++) acc = fmaf(fsm[r * CIN + f], wcol[f], acc);
        g_fproj[(size_t)(row0 + r) * CO + c] = acc;
    }
}

__device__ __forceinline__ float y1_val(const float* __restrict__ pos, int row,
                                        int gid, int c, float w0, float w1, float w2) {
    float fp = __ldg(&g_fproj[(size_t)gid * CO + c]);
    const float* pp = pos + (size_t)row * 3;
    return fmaf(__ldg(pp + 2), w2, fmaf(__ldg(pp + 1), w1, fmaf(__ldg(pp), w0, fp)));
}

// ---------------- K4: layer-1 pre-BN stats ----------------
__global__ void __launch_bounds__(256) k_stats1(const float* __restrict__ pos,
                                                const float* __restrict__ W1) {
    __shared__ float red[256];
    int tid = threadIdx.x;
    int c = tid & 127, h = tid >> 7;
    float w0 = W1[64 * CO + c], w1 = W1[65 * CO + c], w2 = W1[66 * CO + c];
    int row0 = blockIdx.x * 256 + h * 128;
    float s = 0.f, ss = 0.f;
#pragma unroll 8
    for (int i = 0; i < 128; i++) {
        int row = row0 + i;
        int gid = __ldg(&g_idx[row]);
        float y = y1_val(pos, row, gid, c, w0, w1, w2);
        s += y; ss = fmaf(y, y, ss);
    }
    __syncthreads();
    if (h == 1) { red[c] = s; red[128 + c] = ss; }
    __syncthreads();
    if (h == 0) {
        g_part1[blockIdx.x * 256 + c]       = s + red[c];
        g_part1[blockIdx.x * 256 + 128 + c] = ss + red[128 + c];
    }
}

// ---------------- stage-1 reduce ----------------
__global__ void __launch_bounds__(256) k_reduce(int which, int per) {
    const float* src = (which == 0) ? g_part1 : g_part2;
    int col = threadIdx.x;
    int b0 = blockIdx.x * per;
    float a = 0.f;
    for (int i = 0; i < per; i++) a += src[(size_t)(b0 + i) * 256 + col];
    g_partr[(size_t)which * 64 * 256 + blockIdx.x * 256 + col] = a;
}

// ---------------- BN finalize ----------------
__global__ void k_bn(int which, const float* __restrict__ gamma,
                     const float* __restrict__ beta) {
    int c = threadIdx.x;
    const float* part = g_partr + (size_t)which * 64 * 256;
    float s = 0.f, ss = 0.f;
#pragma unroll 8
    for (int i = 0; i < 64; i++) {
        s  += part[i * 256 + c];
        ss += part[i * 256 + 128 + c];
    }
    const float inv = 1.f / (float)NROWS;
    float mean = s * inv;
    float var  = fmaf(-mean, mean, ss * inv);
    float sc   = gamma[c] * rsqrtf(var + BN_EPS);
    float sh   = fmaf(-mean, sc, beta[c]);
    if (which == 0) { g_scale1[c] = sc; g_shift1[c] = sh; }
    else            { g_scale2[c] = sc; g_shift2[c] = sh; }
}

// ---------------- shared GEMM core ----------------
__device__ __forceinline__ void gemm_tile(uint32_t sb, int tid, float acc[8][4]) {
    int w = tid >> 5, lane = tid & 31;
    uint32_t a_lane = (uint32_t)((lane & 15) * PA + (lane & 16));
    uint32_t b_lane = (uint32_t)(((lane & 7) + ((lane & 16) >> 1)) * PA
                                 + ((lane & 8) << 1));
    uint32_t m_off = (uint32_t)((w >> 1) * 16 * PA);
    uint32_t n_off = (uint32_t)((w & 1) * 64 * PA);

    const uint32_t abase[3] = {sb + OFF_AH, sb + OFF_AH, sb + OFF_AL};
    const uint32_t bbase[3] = {sb + OFF_BH, sb + OFF_BL, sb + OFF_BH};

#pragma unroll
    for (int t = 0; t < 3; t++) {
        uint32_t ab = abase[t] + m_off + a_lane;
        uint32_t bb = bbase[t] + n_off + b_lane;
#pragma unroll
        for (int ks = 0; ks < 8; ks++) {
            uint32_t a[4];
            ldm4(a, ab + ks * 32);
#pragma unroll
            for (int npl = 0; npl < 4; npl++) {
                uint32_t b[4];
                ldm4(b, bb + npl * 16 * PA + ks * 32);
                mma16816(acc[2 * npl],     a, b);
                mma16816(acc[2 * npl + 1], a, b + 2);
            }
        }
    }
}

// ---------------- K6: layer2 (4 chunks of 128 rows) + fused stats2 --------------
__global__ void __launch_bounds__(512, 1) k_layer2(const float* __restrict__ pos,
                                                   const float* __restrict__ W1,
                                                   const float* __restrict__ W2,
                                                   const float* __restrict__ b2v) {
    extern __shared__ char smem[];
    uint32_t sb = smem_u32(smem);
    int tid = threadIdx.x;
    int blockrow = blockIdx.x * ROWS_PB;

    w_split(smem, W2, tid);                  // B tiles persist across chunks

    int c0 = (tid & 63) * 2;
    int rg6 = tid >> 6;
    float2 w0 = *reinterpret_cast<const float2*>(&W1[64 * CO + c0]);
    float2 w1v = *reinterpret_cast<const float2*>(&W1[65 * CO + c0]);
    float2 w2v = *reinterpret_cast<const float2*>(&W1[66 * CO + c0]);
    float2 sc = make_float2(g_scale1[c0], g_scale1[c0 + 1]);
    float2 sh = make_float2(g_shift1[c0], g_shift1[c0 + 1]);

    int w = tid >> 5, lane = tid & 31;
    int r = lane >> 2, cq = (lane & 3) * 2;
    int m0 = (w >> 1) * 16;
    int cc = (tid & 31) * 4;
    int rg = tid >> 5;
    float4 bb = __ldg(reinterpret_cast<const float4*>(&b2v[cc]));
    float s[4] = {0, 0, 0, 0}, ss[4] = {0, 0, 0, 0};
    float* stg = reinterpret_cast<float*>(smem);

    for (int chunk = 0; chunk < CHUNKS; chunk++) {
        int rowbase = blockrow + chunk * 128;
        __syncthreads();                     // prior staging reads done; A free

#pragma unroll 4
        for (int rr = 0; rr < 16; rr++) {
            int m = rg6 * 16 + rr;
            int row = rowbase + m;
            int gid = __ldg(&g_idx[row]);
            float2 fp = *reinterpret_cast<const float2*>(
                &g_fproj[(size_t)gid * CO + c0]);
            const float* pp = pos + (size_t)row * 3;
            float p0 = __ldg(pp), p1 = __ldg(pp + 1), p2 = __ldg(pp + 2);
            float ya = fmaf(p2, w2v.x, fmaf(p1, w1v.x, fmaf(p0, w0.x, fp.x)));
            float yb = fmaf(p2, w2v.y, fmaf(p1, w1v.y, fmaf(p0, w0.y, fp.y)));
            float ha = fmaxf(fmaf(ya, sc.x, sh.x), 0.f);
            float hb = fmaxf(fmaf(yb, sc.y, sh.y), 0.f);
            split_store(smem, (uint32_t)(m * PA + c0 * 2), ha, hb);
        }
        __syncthreads();

        float acc[8][4];
#pragma unroll
        for (int i = 0; i < 8; i++)
#pragma unroll
            for (int j = 0; j < 4; j++) acc[i][j] = 0.f;
        gemm_tile(sb, tid, acc);
        __syncthreads();                     // A reads done; stage into A region

#pragma unroll
        for (int ntl = 0; ntl < 8; ntl++) {
            int col = ((w & 1) * 8 + ntl) * 8 + cq;
            stg[(m0 + r) * STG_PITCH + col]         = acc[ntl][0];
            stg[(m0 + r) * STG_PITCH + col + 1]     = acc[ntl][1];
            stg[(m0 + r + 8) * STG_PITCH + col]     = acc[ntl][2];
            stg[(m0 + r + 8) * STG_PITCH + col + 1] = acc[ntl][3];
        }
        __syncthreads();

#pragma unroll
        for (int it = 0; it < 8; it++) {
            int rrow = rg + it * 16;
            float4 v = *reinterpret_cast<float4*>(&stg[rrow * STG_PITCH + cc]);
            v.x += bb.x; v.y += bb.y; v.z += bb.z; v.w += bb.w;
            *reinterpret_cast<float4*>(
                &g_y2[(size_t)(rowbase + rrow) * CO + cc]) = v;
            s[0] += v.x;  ss[0] = fmaf(v.x, v.x, ss[0]);
            s[1] += v.y;  ss[1] = fmaf(v.y, v.y, ss[1]);
            s[2] += v.z;  ss[2] = fmaf(v.z, v.z, ss[2]);
            s[3] += v.w;  ss[3] = fmaf(v.w, v.w, ss[3]);
        }
    }

    // block reduction of stats (A region free after final sync)
    __syncthreads();
    float* red = reinterpret_cast<float*>(smem);
#pragma unroll
    for (int i = 0; i < 4; i++) {
        red[rg * 128 + cc + i]        = s[i];
        red[2048 + rg * 128 + cc + i] = ss[i];
    }
    __syncthreads();
    if (tid < 128) {
        float a = 0.f;
        for (int g = 0; g < 16; g++) a += red[g * 128 + tid];
        g_part2[(size_t)blockIdx.x * 256 + tid] = a;
    } else if (tid < 256) {
        int ch = tid - 128;
        float a = 0.f;
        for (int g = 0; g < 16; g++) a += red[2048 + g * 128 + ch];
        g_part2[(size_t)blockIdx.x * 256 + 128 + ch] = a;
    }
}

// ---------------- K8: layer3 (4 chunks) -> max over K (+b3) ----------------
__global__ void __launch_bounds__(512, 1) k_layer3(const float* __restrict__ W3,
                                                   const float* __restrict__ b3v,
                                                   float* __restrict__ out) {
    extern __shared__ char smem[];
    uint32_t sb = smem_u32(smem);
    int tid = threadIdx.x;
    int blockrow = blockIdx.x * ROWS_PB;

    w_split(smem, W3, tid);

    int c0 = (tid & 63) * 2;
    int rg6 = tid >> 6;
    float2 sc = make_float2(g_scale2[c0], g_scale2[c0 + 1]);
    float2 sh = make_float2(g_shift2[c0], g_shift2[c0 + 1]);
    int w = tid >> 5, lane = tid & 31;

    for (int chunk = 0; chunk < CHUNKS; chunk++) {
        int rowbase = blockrow + chunk * 128;
        __syncthreads();                     // A free (first iter: also after w_split)

#pragma unroll 4
        for (int rr = 0; rr < 16; rr++) {
            int m = rg6 * 16 + rr;
            float2 y = *reinterpret_cast<const float2*>(
                &g_y2[(size_t)(rowbase + m) * CO + c0]);
            float ha = fmaxf(fmaf(y.x, sc.x, sh.x), 0.f);
            float hb = fmaxf(fmaf(y.y, sc.y, sh.y), 0.f);
            split_store(smem, (uint32_t)(m * PA + c0 * 2), ha, hb);
        }
        __syncthreads();

        float acc[8][4];
#pragma unroll
        for (int i = 0; i < 8; i++)
#pragma unroll
            for (int j = 0; j < 4; j++) acc[i][j] = 0.f;
        gemm_tile(sb, tid, acc);

        float cm0[8], cm1[8];
#pragma unroll
        for (int ntl = 0; ntl < 8; ntl++) {
            cm0[ntl] = fmaxf(acc[ntl][0], acc[ntl][2]);
            cm1[ntl] = fmaxf(acc[ntl][1], acc[ntl][3]);
        }
#pragma unroll
        for (int off = 4; off < 32; off <<= 1) {
#pragma unroll
            for (int ntl = 0; ntl < 8; ntl++) {
                cm0[ntl] = fmaxf(cm0[ntl],
                                 __shfl_xor_sync(0xffffffffu, cm0[ntl], off));
                cm1[ntl] = fmaxf(cm1[ntl],
                                 __shfl_xor_sync(0xffffffffu, cm1[ntl], off));
            }
        }
        if (lane < 4) {
            int p = (rowbase >> 4) + (w >> 1);
#pragma unroll
            for (int ntl = 0; ntl < 8; ntl++) {
                int col = ((w & 1) * 8 + ntl) * 8 + lane * 2;
                out[(size_t)p * CO + col]     = cm0[ntl] + __ldg(&b3v[col]);
                out[(size_t)p * CO + col + 1] = cm1[ntl] + __ldg(&b3v[col + 1]);
            }
        }
    }
}

// ---------------- launch ----------------
extern "C" void kernel_launch(void* const* d_in, const int* in_sizes, int n_in,
                              void* d_out, int out_size) {
    const float* features = (const float*)d_in[0];
    const float* pos      = (const float*)d_in[1];
    const float* W1  = (const float*)d_in[2];
    const float* b1  = (const float*)d_in[3];
    const float* g1  = (const float*)d_in[4];
    const float* bt1 = (const float*)d_in[5];
    const float* W2  = (const float*)d_in[6];
    const float* b2  = (const float*)d_in[7];
    const float* g2  = (const float*)d_in[8];
    const float* bt2 = (const float*)d_in[9];
    const float* W3  = (const float*)d_in[10];
    const float* b3  = (const float*)d_in[11];
    float* out = (float*)d_out;

    cudaFuncSetAttribute(k_layer2, cudaFuncAttributeMaxDynamicSharedMemorySize, SMEM_T);
    cudaFuncSetAttribute(k_layer3, cudaFuncAttributeMaxDynamicSharedMemorySize, SMEM_T);

    k_prep<<<NPTS / 128, 128>>>(pos);
    k_fproj<<<NPTS / 32, 128>>>(features, W1, b1);
    k_knn<<<dim3(NN / QW, BB), QW * 32>>>();
    k_stats1<<<2048, 256>>>(pos, W1);
    k_reduce<<<64, 256>>>(0, 32);
    k_bn<<<1, 128>>>(0, g1, bt1);
    k_layer2<<<NROWS / ROWS_PB, 512, SMEM_T>>>(pos, W1, W2, b2);
    k_reduce<<<64, 256>>>(1, 16);
    k_bn<<<1, 128>>>(1, g2, bt2);
    k_layer3<<<NROWS / ROWS_PB, 512, SMEM_T>>>(W3, b3, out);
}

// round 15
// speedup vs baseline: 1.1983x; 1.0300x over previous
#include <cuda_runtime.h>
#include <cuda_bf16.h>
#include <cstdint>

#define BB 4
#define NN 8192
#define CIN 64
#define KK 16
#define CO 128
#define NROWS (BB*NN*KK)   /* 524288 */
#define NPTS (BB*NN)       /* 32768  */
#define BN_EPS 1e-5f

typedef unsigned long long ull;

// ---------------- scratch (device globals) ----------------
__device__ float4 g_pts[NPTS];
__device__ int    g_idx[NROWS];
__device__ float  g_fproj[(size_t)NPTS*CO];
__device__ float  g_y2[(size_t)NROWS*CO];
__device__ float  g_part1[2048*256];
__device__ float  g_part2[4096*256];
__device__ float  g_partr[2*64*256];
__device__ float  g_scale1[CO], g_shift1[CO];
__device__ float  g_scale2[CO], g_shift2[CO];

__device__ __forceinline__ uint32_t smem_u32(const void* p) {
    uint32_t a;
    asm("{ .reg .u64 t; cvta.to.shared.u64 t, %1; cvt.u32.u64 %0, t; }"
        : "=r"(a) : "l"(p));
    return a;
}

// ---------------- arch-neutral tensor ops (sm_80+ PTX) ----------------
__device__ __forceinline__ void ldm4(uint32_t* r, uint32_t addr) {
    asm volatile("ldmatrix.sync.aligned.m8n8.x4.shared.b16 {%0,%1,%2,%3}, [%4];"
                 : "=r"(r[0]), "=r"(r[1]), "=r"(r[2]), "=r"(r[3]) : "r"(addr));
}
__device__ __forceinline__ void mma16816(float* c, const uint32_t* a,
                                         const uint32_t* b) {
    asm volatile(
        "mma.sync.aligned.m16n8k16.row.col.f32.bf16.bf16.f32 "
        "{%0,%1,%2,%3}, {%4,%5,%6,%7}, {%8,%9}, {%0,%1,%2,%3};"
        : "+f"(c[0]), "+f"(c[1]), "+f"(c[2]), "+f"(c[3])
        : "r"(a[0]), "r"(a[1]), "r"(a[2]), "r"(a[3]), "r"(b[0]), "r"(b[1]));
}

// 64-row A tiles, full 128x128 B tiles; 102 KB total -> 2 blocks/SM
#define PA 272
#define OFF_AH 0
#define OFF_AL 17408
#define OFF_BH 34816
#define OFF_BL 69632
#define SMEM_T 104448
#define STG_PITCH 132
#define ROWS_PC 64                /* rows per chunk */
#define CHUNKS 8
#define ROWS_PB (ROWS_PC * CHUNKS)   /* 512 rows per block */

__device__ __forceinline__ void split_store(char* smem, uint32_t o,
                                            float a, float b) {
    __nv_bfloat16 ah = __float2bfloat16(a), bh = __float2bfloat16(b);
    float al = a - __bfloat162float(ah), bl = b - __bfloat162float(bh);
    *reinterpret_cast<__nv_bfloat162*>(smem + OFF_AH + o) = __halves2bfloat162(ah, bh);
    *reinterpret_cast<__nv_bfloat162*>(smem + OFF_AL + o) =
        __halves2bfloat162(__float2bfloat16(al), __float2bfloat16(bl));
}

__device__ __forceinline__ void w_split(char* smem, const float* __restrict__ W,
                                        int tid) {
    for (int i = tid; i < CO * CO; i += 256) {
        int n = i & 127, k = i >> 7;
        float w = W[k * CO + n];
        __nv_bfloat16 hi = __float2bfloat16(w);
        float lo = w - __bfloat162float(hi);
        uint32_t o = (uint32_t)(n * PA + k * 2);
        *reinterpret_cast<__nv_bfloat16*>(smem + OFF_BH + o) = hi;
        *reinterpret_cast<__nv_bfloat16*>(smem + OFF_BL + o) = __float2bfloat16(lo);
    }
}

// ---------------- K1 ----------------
__global__ void k_prep(const float* __restrict__ pos) {
    int p = blockIdx.x * 128 + threadIdx.x;
    const float* q = pos + (size_t)p * KK * 3;
    float sx = 0.f, sy = 0.f, sz = 0.f;
#pragma unroll
    for (int k = 0; k < KK; k++) { sx += q[k*3]; sy += q[k*3+1]; sz += q[k*3+2]; }
    float x = sx * 0.0625f, y = sy * 0.0625f, z = sz * 0.0625f;
    float sq = fmaf(z, z, fmaf(y, y, x * x));
    g_pts[p] = make_float4(x, y, z, sq);
}

// ---------------- K2: warp-per-query KNN, replicated-list bubble (proven) -------
template<int S>
__device__ __forceinline__ void bub_from(float (&dist)[KK], int (&id)[KK],
                                         float vd, int vi) {
#pragma unroll
    for (int s = S; s < KK; s++) {
        bool p = vd < dist[s];
        float td = dist[s]; int ti = id[s];
        dist[s] = p ? vd : dist[s];
        id[s]   = p ? vi : id[s];
        vd = p ? td : vd;
        vi = p ? ti : vi;
    }
}

#define QW 8
#define TSZ 1024
__global__ void __launch_bounds__(QW*32) k_knn() {
    __shared__ float4 tile[TSZ];
    const unsigned FULL = 0xffffffffu;
    int lane = threadIdx.x & 31;
    int wid  = threadIdx.x >> 5;
    int b = blockIdx.y;
    int q = blockIdx.x * QW + wid;
    float4 me = g_pts[b * NN + q];

    float dist[KK]; int id[KK];
#pragma unroll
    for (int i = 0; i < KK; i++) { dist[i] = 3.4e38f; id[i] = 0; }

    for (int t = 0; t < NN; t += TSZ) {
        __syncthreads();
        for (int i = threadIdx.x; i < TSZ; i += QW*32)
            tile[i] = g_pts[b * NN + t + i];
        __syncthreads();

        for (int j0 = 0; j0 < TSZ; j0 += 32) {
            float4 c = tile[j0 + lane];
            float dot = fmaf(me.z, c.z, fmaf(me.y, c.y, me.x * c.x));
            float d = fmaf(-2.f, dot, me.w + c.w);
            int cid = t + j0 + lane;

            unsigned mask = __ballot_sync(FULL, d < dist[KK-1]);
            while (mask) {
                int src = __ffs(mask) - 1;
                float vd = __shfl_sync(FULL, d, src);
                int   vi = __shfl_sync(FULL, cid, src);
                if (vd < dist[7]) {
                    if (vd < dist[3]) bub_from<0>(dist, id, vd, vi);
                    else              bub_from<4>(dist, id, vd, vi);
                } else {
                    if (vd < dist[11]) bub_from<8>(dist, id, vd, vi);
                    else               bub_from<12>(dist, id, vd, vi);
                }
                unsigned above = (src < 31) ? (0xFFFFFFFEu << src) : 0u;
                mask = __ballot_sync(FULL, d < dist[KK-1]) & above;
            }
        }
    }
    if (lane == 0) {
        int4* dst = reinterpret_cast<int4*>(&g_idx[(b * NN + q) * KK]);
        int base = b * NN;
        dst[0] = make_int4(base + id[0],  base + id[1],  base + id[2],  base + id[3]);
        dst[1] = make_int4(base + id[4],  base + id[5],  base + id[6],  base + id[7]);
        dst[2] = make_int4(base + id[8],  base + id[9],  base + id[10], base + id[11]);
        dst[3] = make_int4(base + id[12], base + id[13], base + id[14], base + id[15]);
    }
}

// ---------------- K3: Fproj = b1 + features @ W1[:64,:] ----------------
__global__ void __launch_bounds__(128) k_fproj(const float* __restrict__ feat,
                                               const float* __restrict__ W1,
                                               const float* __restrict__ b1) {
    int c = threadIdx.x;
    int row0 = blockIdx.x * 32;
    __shared__ float fsm[32 * CIN];
    for (int i = c; i < 32 * CIN; i += 128) fsm[i] = feat[(size_t)row0 * CIN + i];
    float wcol[CIN];
#pragma unroll
    for (int f = 0; f < CIN; f++) wcol[f] = W1[f * CO + c];
    float bc = b1[c];
    __syncthreads();
    for (int r = 0; r < 32; r++) {
        float acc = bc;
#pragma unroll
        for (int f = 0; f < CIN; f++) acc = fmaf(fsm[r * CIN + f], wcol[f], acc);
        g_fproj[(size_t)(row0 + r) * CO + c] = acc;
    }
}

__device__ __forceinline__ float y1_val(const float* __restrict__ pos, int row,
                                        int gid, int c, float w0, float w1, float w2) {
    float fp = __ldg(&g_fproj[(size_t)gid * CO + c]);
    const float* pp = pos + (size_t)row * 3;
    return fmaf(__ldg(pp + 2), w2, fmaf(__ldg(pp + 1), w1, fmaf(__ldg(pp), w0, fp)));
}

// ---------------- K4: layer-1 pre-BN stats ----------------
__global__ void __launch_bounds__(256) k_stats1(const float* __restrict__ pos,
                                                const float* __restrict__ W1) {
    __shared__ float red[256];
    int tid = threadIdx.x;
    int c = tid & 127, h = tid >> 7;
    float w0 = W1[64 * CO + c], w1 = W1[65 * CO + c], w2 = W1[66 * CO + c];
    int row0 = blockIdx.x * 256 + h * 128;
    float s = 0.f, ss = 0.f;
#pragma unroll 8
    for (int i = 0; i < 128; i++) {
        int row = row0 + i;
        int gid = __ldg(&g_idx[row]);
        float y = y1_val(pos, row, gid, c, w0, w1, w2);
        s += y; ss = fmaf(y, y, ss);
    }
    __syncthreads();
    if (h == 1) { red[c] = s; red[128 + c] = ss; }
    __syncthreads();
    if (h == 0) {
        g_part1[blockIdx.x * 256 + c]       = s + red[c];
        g_part1[blockIdx.x * 256 + 128 + c] = ss + red[128 + c];
    }
}

// ---------------- stage-1 reduce ----------------
__global__ void __launch_bounds__(256) k_reduce(int which, int per) {
    const float* src = (which == 0) ? g_part1 : g_part2;
    int col = threadIdx.x;
    int b0 = blockIdx.x * per;
    float a = 0.f;
    for (int i = 0; i < per; i++) a += src[(size_t)(b0 + i) * 256 + col];
    g_partr[(size_t)which * 64 * 256 + blockIdx.x * 256 + col] = a;
}

// ---------------- BN finalize ----------------
__global__ void k_bn(int which, const float* __restrict__ gamma,
                     const float* __restrict__ beta) {
    int c = threadIdx.x;
    const float* part = g_partr + (size_t)which * 64 * 256;
    float s = 0.f, ss = 0.f;
#pragma unroll 8
    for (int i = 0; i < 64; i++) {
        s  += part[i * 256 + c];
        ss += part[i * 256 + 128 + c];
    }
    const float inv = 1.f / (float)NROWS;
    float mean = s * inv;
    float var  = fmaf(-mean, mean, ss * inv);
    float sc   = gamma[c] * rsqrtf(var + BN_EPS);
    float sh   = fmaf(-mean, sc, beta[c]);
    if (which == 0) { g_scale1[c] = sc; g_shift1[c] = sh; }
    else            { g_scale2[c] = sc; g_shift2[c] = sh; }
}

// ---------------- shared GEMM core: 8 warps, warp = 16 rows x 64 cols -----------
__device__ __forceinline__ void gemm_tile(uint32_t sb, int tid, float acc[8][4]) {
    int w = tid >> 5, lane = tid & 31;
    uint32_t a_lane = (uint32_t)((lane & 15) * PA + (lane & 16));
    uint32_t b_lane = (uint32_t)(((lane & 7) + ((lane & 16) >> 1)) * PA
                                 + ((lane & 8) << 1));
    uint32_t m_off = (uint32_t)((w >> 1) * 16 * PA);
    uint32_t n_off = (uint32_t)((w & 1) * 64 * PA);

    const uint32_t abase[3] = {sb + OFF_AH, sb + OFF_AH, sb + OFF_AL};
    const uint32_t bbase[3] = {sb + OFF_BH, sb + OFF_BL, sb + OFF_BH};

#pragma unroll
    for (int t = 0; t < 3; t++) {
        uint32_t ab = abase[t] + m_off + a_lane;
        uint32_t bb = bbase[t] + n_off + b_lane;
#pragma unroll
        for (int ks = 0; ks < 8; ks++) {
            uint32_t a[4];
            ldm4(a, ab + ks * 32);
#pragma unroll
            for (int npl = 0; npl < 4; npl++) {
                uint32_t b[4];
                ldm4(b, bb + npl * 16 * PA + ks * 32);
                mma16816(acc[2 * npl],     a, b);
                mma16816(acc[2 * npl + 1], a, b + 2);
            }
        }
    }
}

// ---------------- K6: layer2 (8 chunks of 64 rows) + fused stats2 ---------------
__global__ void __launch_bounds__(256, 2) k_layer2(const float* __restrict__ pos,
                                                   const float* __restrict__ W1,
                                                   const float* __restrict__ W2,
                                                   const float* __restrict__ b2v) {
    extern __shared__ char smem[];
    uint32_t sb = smem_u32(smem);
    int tid = threadIdx.x;
    int blockrow = blockIdx.x * ROWS_PB;

    w_split(smem, W2, tid);                  // B tiles persist across chunks

    int c0 = (tid & 63) * 2;
    int rg6 = tid >> 6;                      // 0..3 -> 16-row group
    float2 w0 = *reinterpret_cast<const float2*>(&W1[64 * CO + c0]);
    float2 w1v = *reinterpret_cast<const float2*>(&W1[65 * CO + c0]);
    float2 w2v = *reinterpret_cast<const float2*>(&W1[66 * CO + c0]);
    float2 sc = make_float2(g_scale1[c0], g_scale1[c0 + 1]);
    float2 sh = make_float2(g_shift1[c0], g_shift1[c0 + 1]);

    int w = tid >> 5, lane = tid & 31;
    int r = lane >> 2, cq = (lane & 3) * 2;
    int m0 = (w >> 1) * 16;
    int cc = (tid & 31) * 4;
    int rg = tid >> 5;                       // 0..7
    float4 bb = __ldg(reinterpret_cast<const float4*>(&b2v[cc]));
    float s[4] = {0, 0, 0, 0}, ss[4] = {0, 0, 0, 0};
    float* stg = reinterpret_cast<float*>(smem);

    for (int chunk = 0; chunk < CHUNKS; chunk++) {
        int rowbase = blockrow + chunk * ROWS_PC;
        __syncthreads();                     // prior staging reads done; A free

#pragma unroll 4
        for (int rr = 0; rr < 16; rr++) {
            int m = rg6 * 16 + rr;
            int row = rowbase + m;
            int gid = __ldg(&g_idx[row]);
            float2 fp = *reinterpret_cast<const float2*>(
                &g_fproj[(size_t)gid * CO + c0]);
            const float* pp = pos + (size_t)row * 3;
            float p0 = __ldg(pp), p1 = __ldg(pp + 1), p2 = __ldg(pp + 2);
            float ya = fmaf(p2, w2v.x, fmaf(p1, w1v.x, fmaf(p0, w0.x, fp.x)));
            float yb = fmaf(p2, w2v.y, fmaf(p1, w1v.y, fmaf(p0, w0.y, fp.y)));
            float ha = fmaxf(fmaf(ya, sc.x, sh.x), 0.f);
            float hb = fmaxf(fmaf(yb, sc.y, sh.y), 0.f);
            split_store(smem, (uint32_t)(m * PA + c0 * 2), ha, hb);
        }
        __syncthreads();

        float acc[8][4];
#pragma unroll
        for (int i = 0; i < 8; i++)
#pragma unroll
            for (int j = 0; j < 4; j++) acc[i][j] = 0.f;
        gemm_tile(sb, tid, acc);
        __syncthreads();                     // A reads done; stage into A region

#pragma unroll
        for (int ntl = 0; ntl < 8; ntl++) {
            int col = ((w & 1) * 8 + ntl) * 8 + cq;
            stg[(m0 + r) * STG_PITCH + col]         = acc[ntl][0];
            stg[(m0 + r) * STG_PITCH + col + 1]     = acc[ntl][1];
            stg[(m0 + r + 8) * STG_PITCH + col]     = acc[ntl][2];
            stg[(m0 + r + 8) * STG_PITCH + col + 1] = acc[ntl][3];
        }
        __syncthreads();

#pragma unroll
        for (int it = 0; it < 8; it++) {
            int rrow = rg + it * 8;
            float4 v = *reinterpret_cast<float4*>(&stg[rrow * STG_PITCH + cc]);
            v.x += bb.x; v.y += bb.y; v.z += bb.z; v.w += bb.w;
            *reinterpret_cast<float4*>(
                &g_y2[(size_t)(rowbase + rrow) * CO + cc]) = v;
            s[0] += v.x;  ss[0] = fmaf(v.x, v.x, ss[0]);
            s[1] += v.y;  ss[1] = fmaf(v.y, v.y, ss[1]);
            s[2] += v.z;  ss[2] = fmaf(v.z, v.z, ss[2]);
            s[3] += v.w;  ss[3] = fmaf(v.w, v.w, ss[3]);
        }
    }

    // block reduction of stats (A region free after final sync)
    __syncthreads();
    float* red = reinterpret_cast<float*>(smem);
#pragma unroll
    for (int i = 0; i < 4; i++) {
        red[rg * 128 + cc + i]        = s[i];
        red[1024 + rg * 128 + cc + i] = ss[i];
    }
    __syncthreads();
    if (tid < 128) {
        float a = 0.f;
        for (int g = 0; g < 8; g++) a += red[g * 128 + tid];
        g_part2[(size_t)blockIdx.x * 256 + tid] = a;
    } else {
        int ch = tid - 128;
        float a = 0.f;
        for (int g = 0; g < 8; g++) a += red[1024 + g * 128 + ch];
        g_part2[(size_t)blockIdx.x * 256 + 128 + ch] = a;
    }
}

// ---------------- K8: layer3 (8 chunks of 64 rows) -> max over K (+b3) ----------
__global__ void __launch_bounds__(256, 2) k_layer3(const float* __restrict__ W3,
                                                   const float* __restrict__ b3v,
                                                   float* __restrict__ out) {
    extern __shared__ char smem[];
    uint32_t sb = smem_u32(smem);
    int tid = threadIdx.x;
    int blockrow = blockIdx.x * ROWS_PB;

    w_split(smem, W3, tid);

    int c0 = (tid & 63) * 2;
    int rg6 = tid >> 6;
    float2 sc = make_float2(g_scale2[c0], g_scale2[c0 + 1]);
    float2 sh = make_float2(g_shift2[c0], g_shift2[c0 + 1]);
    int w = tid >> 5, lane = tid & 31;

    for (int chunk = 0; chunk < CHUNKS; chunk++) {
        int rowbase = blockrow + chunk * ROWS_PC;
        __syncthreads();

#pragma unroll 4
        for (int rr = 0; rr < 16; rr++) {
            int m = rg6 * 16 + rr;
            float2 y = *reinterpret_cast<const float2*>(
                &g_y2[(size_t)(rowbase + m) * CO + c0]);
            float ha = fmaxf(fmaf(y.x, sc.x, sh.x), 0.f);
            float hb = fmaxf(fmaf(y.y, sc.y, sh.y), 0.f);
            split_store(smem, (uint32_t)(m * PA + c0 * 2), ha, hb);
        }
        __syncthreads();

        float acc[8][4];
#pragma unroll
        for (int i = 0; i < 8; i++)
#pragma unroll
            for (int j = 0; j < 4; j++) acc[i][j] = 0.f;
        gemm_tile(sb, tid, acc);

        // warp's 16 rows = one point; max over rows (exactly commutative)
        float cm0[8], cm1[8];
#pragma unroll
        for (int ntl = 0; ntl < 8; ntl++) {
            cm0[ntl] = fmaxf(acc[ntl][0], acc[ntl][2]);
            cm1[ntl] = fmaxf(acc[ntl][1], acc[ntl][3]);
        }
#pragma unroll
        for (int off = 4; off < 32; off <<= 1) {
#pragma unroll
            for (int ntl = 0; ntl < 8; ntl++) {
                cm0[ntl] = fmaxf(cm0[ntl],
                                 __shfl_xor_sync(0xffffffffu, cm0[ntl], off));
                cm1[ntl] = fmaxf(cm1[ntl],
                                 __shfl_xor_sync(0xffffffffu, cm1[ntl], off));
            }
        }
        if (lane < 4) {
            int p = (rowbase >> 4) + (w >> 1);
#pragma unroll
            for (int ntl = 0; ntl < 8; ntl++) {
                int col = ((w & 1) * 8 + ntl) * 8 + lane * 2;
                out[(size_t)p * CO + col]     = cm0[ntl] + __ldg(&b3v[col]);
                out[(size_t)p * CO + col + 1] = cm1[ntl] + __ldg(&b3v[col + 1]);
            }
        }
    }
}

// ---------------- launch ----------------
extern "C" void kernel_launch(void* const* d_in, const int* in_sizes, int n_in,
                              void* d_out, int out_size) {
    const float* features = (const float*)d_in[0];
    const float* pos      = (const float*)d_in[1];
    const float* W1  = (const float*)d_in[2];
    const float* b1  = (const float*)d_in[3];
    const float* g1  = (const float*)d_in[4];
    const float* bt1 = (const float*)d_in[5];
    const float* W2  = (const float*)d_in[6];
    const float* b2  = (const float*)d_in[7];
    const float* g2  = (const float*)d_in[8];
    const float* bt2 = (const float*)d_in[9];
    const float* W3  = (const float*)d_in[10];
    const float* b3  = (const float*)d_in[11];
    float* out = (float*)d_out;

    cudaFuncSetAttribute(k_layer2, cudaFuncAttributeMaxDynamicSharedMemorySize, SMEM_T);
    cudaFuncSetAttribute(k_layer3, cudaFuncAttributeMaxDynamicSharedMemorySize, SMEM_T);

    k_prep<<<NPTS / 128, 128>>>(pos);
    k_fproj<<<NPTS / 32, 128>>>(features, W1, b1);
    k_knn<<<dim3(NN / QW, BB), QW * 32>>>();
    k_stats1<<<2048, 256>>>(pos, W1);
    k_reduce<<<64, 256>>>(0, 32);
    k_bn<<<1, 128>>>(0, g1, bt1);
    k_layer2<<<NROWS / ROWS_PB, 256, SMEM_T>>>(pos, W1, W2, b2);
    k_reduce<<<64, 256>>>(1, 16);
    k_bn<<<1, 128>>>(1, g2, bt2);
    k_layer3<<<NROWS / ROWS_PB, 256, SMEM_T>>>(W3, b3, out);
}